// round 11
// baseline (speedup 1.0000x reference)
#include <cuda_runtime.h>
#include <cuda_fp16.h>
#include <cstdint>

// Problem constants (fixed by setup_inputs)
#define T_TOK   8192      // B*S = 4*2048
#define D_IN    2048
#define D_OUT   2048
#define R_RANK  64
#define N_EXP   16
#define N_COLS  80        // R + E combined small-GEMM width

// ---------------- device scratch (no allocations allowed) ----------------
__device__ float g_S[T_TOK * N_COLS];        // [token][0..63]=res_hidden, [64..79]=router logits
__device__ int   g_cnt[N_EXP];
__device__ int   g_tok[N_EXP * T_TOK];
__device__ float g_wt [N_EXP * T_TOK];
// fp16 copies for the tensor-core GEMMs
__device__ __half g_xh[T_TOK * D_IN];
__device__ __half g_wh[D_OUT * D_IN];
__device__ __half g_bh[N_EXP * D_OUT * R_RANK];

// ---------------- helpers ----------------
__device__ __forceinline__ uint32_t smem_u32(const void* p) {
    uint32_t a;
    asm("{ .reg .u64 t; cvta.to.shared.u64 t, %1; cvt.u32.u64 %0, t; }" : "=r"(a) : "l"(p));
    return a;
}
__device__ __forceinline__ void cp16(uint32_t s, const void* g) {
    asm volatile("cp.async.cg.shared.global [%0], [%1], 16;" :: "r"(s), "l"(g) : "memory");
}
__device__ __forceinline__ void ldmatrix_x4(uint32_t* r, uint32_t addr) {
    asm volatile("ldmatrix.sync.aligned.m8n8.x4.shared.b16 {%0,%1,%2,%3}, [%4];"
                 : "=r"(r[0]), "=r"(r[1]), "=r"(r[2]), "=r"(r[3]) : "r"(addr));
}
__device__ __forceinline__ void mma16816h(float* c, const uint32_t* a, uint32_t b0, uint32_t b1) {
    asm volatile(
        "mma.sync.aligned.m16n8k16.row.col.f32.f16.f16.f32 "
        "{%0,%1,%2,%3}, {%4,%5,%6,%7}, {%8,%9}, {%0,%1,%2,%3};"
        : "+f"(c[0]), "+f"(c[1]), "+f"(c[2]), "+f"(c[3])
        : "r"(a[0]), "r"(a[1]), "r"(a[2]), "r"(a[3]), "r"(b0), "r"(b1));
}
__device__ __forceinline__ void red_v2(float* p, float x, float y) {
    asm volatile("red.global.add.v2.f32 [%0], {%1,%2};"
                 :: "l"(p), "f"(x), "f"(y) : "memory");
}
#define CP_COMMIT() asm volatile("cp.async.commit_group;" ::: "memory")
#define CP_WAIT(n)  asm volatile("cp.async.wait_group %0;" :: "n"(n) : "memory")

// ============================================================================
// Kernel 0: fp32 -> fp16 for x and W in ONE launch (grid-stride)
// ============================================================================
__global__ __launch_bounds__(256) void k0_cvt2(
    const float* __restrict__ s1, __half* __restrict__ d1, int n1,
    const float* __restrict__ s2, __half* __restrict__ d2, int n2)
{
    int total = n1 + n2;
    for (int i = blockIdx.x * blockDim.x + threadIdx.x; i < total;
         i += gridDim.x * blockDim.x) {
        const float* src; __half* dst; int j;
        if (i < n1) { src = s1; dst = d1; j = i; }
        else        { src = s2; dst = d2; j = i - n1; }
        float4 v = *(const float4*)&src[(size_t)j * 4];
        __half h[4];
        h[0] = __float2half_rn(v.x); h[1] = __float2half_rn(v.y);
        h[2] = __float2half_rn(v.z); h[3] = __float2half_rn(v.w);
        *(uint2*)&dst[(size_t)j * 4] = *(uint2*)h;
    }
}

__global__ __launch_bounds__(256) void k0_cvt(
    const float* __restrict__ src, __half* __restrict__ dst, int n4)
{
    int i = blockIdx.x * blockDim.x + threadIdx.x;
    if (i >= n4) return;
    float4 v = *(const float4*)&src[(size_t)i * 4];
    __half h[4];
    h[0] = __float2half_rn(v.x); h[1] = __float2half_rn(v.y);
    h[2] = __float2half_rn(v.z); h[3] = __float2half_rn(v.w);
    *(uint2*)&dst[(size_t)i * 4] = *(uint2*)h;
}

// ============================================================================
// Kernel 1: S = x @ [A^T | W_router^T]  (fp32 SIMT)
// ============================================================================
__global__ __launch_bounds__(256) void k1_small_gemm(
    const float* __restrict__ x,
    const float* __restrict__ A,
    const float* __restrict__ Wr)
{
    __shared__ float xs[128][68];
    __shared__ float ws[40][68];

    const int tid = threadIdx.x;
    if (blockIdx.x == 0 && blockIdx.y == 0 && tid < N_EXP) g_cnt[tid] = 0;

    const int m0 = blockIdx.y * 128;
    const int c0 = blockIdx.x * 40;
    const int tg = tid >> 3;
    const int cg = tid & 7;

    float acc[4][5];
#pragma unroll
    for (int i = 0; i < 4; i++)
#pragma unroll
        for (int j = 0; j < 5; j++) acc[i][j] = 0.f;

    for (int k0 = 0; k0 < D_IN; k0 += 64) {
#pragma unroll
        for (int it = 0; it < 8; it++) {
            int q = tid + it * 256;
            int row = q >> 4;
            int kc = (q & 15) << 2;
            float4 v = *(const float4*)&x[(size_t)(m0 + row) * D_IN + k0 + kc];
            *(float4*)&xs[row][kc] = v;
        }
        for (int q = tid; q < 40 * 16; q += 256) {
            int col = q >> 4;
            int kc = (q & 15) << 2;
            int gc = c0 + col;
            const float* src = (gc < R_RANK) ? (A + (size_t)gc * D_IN)
                                             : (Wr + (size_t)(gc - R_RANK) * D_IN);
            float4 v = *(const float4*)&src[k0 + kc];
            *(float4*)&ws[col][kc] = v;
        }
        __syncthreads();

#pragma unroll 16
        for (int kk = 0; kk < 64; kk++) {
            float av[4], bv[5];
#pragma unroll
            for (int i = 0; i < 4; i++) av[i] = xs[tg * 4 + i][kk];
#pragma unroll
            for (int j = 0; j < 5; j++) bv[j] = ws[cg * 5 + j][kk];
#pragma unroll
            for (int i = 0; i < 4; i++)
#pragma unroll
                for (int j = 0; j < 5; j++) acc[i][j] += av[i] * bv[j];
        }
        __syncthreads();
    }

#pragma unroll
    for (int i = 0; i < 4; i++) {
        size_t base = (size_t)(m0 + tg * 4 + i) * N_COLS + c0 + cg * 5;
#pragma unroll
        for (int j = 0; j < 5; j++) g_S[base + j] = acc[i][j];
    }
}

// ============================================================================
// Kernel 2: softmax + top-k + scatter
// ============================================================================
__global__ __launch_bounds__(128) void k2_router(const int* __restrict__ topk_ptr)
{
    int t = blockIdx.x * blockDim.x + threadIdx.x;
    if (t >= T_TOK) return;

    float p[N_EXP];
    float mx = -1e30f;
#pragma unroll
    for (int e = 0; e < N_EXP; e++) {
        p[e] = g_S[(size_t)t * N_COLS + R_RANK + e];
        mx = fmaxf(mx, p[e]);
    }
    float sum = 0.f;
#pragma unroll
    for (int e = 0; e < N_EXP; e++) { p[e] = __expf(p[e] - mx); sum += p[e]; }
    float inv = 1.f / sum;
#pragma unroll
    for (int e = 0; e < N_EXP; e++) p[e] *= inv;

    int k = topk_ptr ? *topk_ptr : 2;

    if (k > 0 && k < N_EXP) {
        unsigned sel = 0;
        float ssum = 0.f;
        for (int it = 0; it < k; it++) {
            int best = -1; float bv = -1.f;
#pragma unroll
            for (int e = 0; e < N_EXP; e++)
                if (!((sel >> e) & 1u) && p[e] > bv) { bv = p[e]; best = e; }
            sel |= 1u << best;
            ssum += bv;
        }
        float denom = 1.f / (ssum + 1e-6f);
#pragma unroll
        for (int e = 0; e < N_EXP; e++) {
            if ((sel >> e) & 1u) {
                float w = p[e] * denom;
                int slot = atomicAdd(&g_cnt[e], 1);
                g_tok[e * T_TOK + slot] = t;
                g_wt [e * T_TOK + slot] = w;
            }
        }
    } else {
#pragma unroll
        for (int e = 0; e < N_EXP; e++) {
            int slot = atomicAdd(&g_cnt[e], 1);
            g_tok[e * T_TOK + slot] = t;
            g_wt [e * T_TOK + slot] = p[e];
        }
    }
}

// ============================================================================
// Kernel 3: base GEMM via mma.sync fp16: out = xh @ wh^T + b
// CTA tile 64x128, 128 threads (4 warps, warp tile 32x64), BK=32,
// 3-stage cp.async, 4 CTAs/SM (independent barrier domains).
// ============================================================================
#define BK       32
#define NCHUNK   (D_IN / BK)                 // 64
#define MAT_A_B  (64 * 80)                   // 5120
#define MAT_B_B  (128 * 80)                  // 10240
#define STAGE_B  (MAT_A_B + MAT_B_B)         // 15360
#define SMEM_K3  (3 * STAGE_B)               // 46080

__global__ __launch_bounds__(128, 4) void k3_mma_gemm(
    const float* __restrict__ bias, float* __restrict__ out)
{
    extern __shared__ char sm[];
    const int tid  = threadIdx.x;
    const int wid  = tid >> 5;
    const int lane = tid & 31;
    const int g    = lane >> 2;      // 0..7
    const int t4   = lane & 3;       // 0..3

    const int m0 = blockIdx.y * 64;
    const int n0 = blockIdx.x * 128;
    const int wm = (wid >> 1) * 32;  // warp M offset (2 groups)
    const int wn = (wid & 1) * 64;   // warp N offset (2 groups)

    const uint32_t sbase = smem_u32(sm);

    const int a_row = ((lane >> 3) & 1) * 8 + (lane & 7);
    const int a_kb  = (lane >> 4) * 16;
    const int b_row = ((lane >> 4) & 1) * 8 + (lane & 7);
    const int b_kb  = ((lane >> 3) & 1) * 16;

    float acc[2][8][4];
#pragma unroll
    for (int mi = 0; mi < 2; mi++)
#pragma unroll
        for (int ni = 0; ni < 8; ni++)
#pragma unroll
            for (int r = 0; r < 4; r++) acc[mi][ni][r] = 0.f;

    // ---- async load of one k-chunk (A 64 rows | B 128 rows) into stage c%3 ----
    auto load_chunk = [&](int c) {
        const uint32_t stg = sbase + (c % 3) * STAGE_B;
        const int k0 = c * BK;
#pragma unroll
        for (int it = 0; it < 6; it++) {
            int q = tid + it * 128;             // 0..767
            if (q < 256) {                      // A: 64 rows x 4 quads
                int row  = q >> 2;
                int quad = q & 3;
                cp16(stg + row * 80 + quad * 16,
                     &g_xh[(size_t)(m0 + row) * D_IN + k0 + quad * 8]);
            } else {                            // B: 128 rows x 4 quads
                int q2   = q - 256;
                int row  = q2 >> 2;
                int quad = q2 & 3;
                cp16(stg + MAT_A_B + row * 80 + quad * 16,
                     &g_wh[(size_t)(n0 + row) * D_IN + k0 + quad * 8]);
            }
        }
        CP_COMMIT();
    };

    load_chunk(0);
    load_chunk(1);

    for (int c = 0; c < NCHUNK; c++) {
        if (c + 2 < NCHUNK) { load_chunk(c + 2); CP_WAIT(2); }
        else if (c + 1 < NCHUNK) { CP_WAIT(1); }
        else { CP_WAIT(0); }
        __syncthreads();

        const uint32_t stg = sbase + (c % 3) * STAGE_B;
        const uint32_t sA = stg;
        const uint32_t sB = stg + MAT_A_B;

#pragma unroll
        for (int ks = 0; ks < 2; ks++) {
            const uint32_t kso = ks * 32;

            uint32_t aH[2][4];
#pragma unroll
            for (int mi = 0; mi < 2; mi++) {
                uint32_t aoff = (uint32_t)((wm + mi * 16 + a_row) * 80) + kso + a_kb;
                ldmatrix_x4(aH[mi], sA + aoff);
            }
            uint32_t bH[8][2];
#pragma unroll
            for (int nj = 0; nj < 4; nj++) {
                uint32_t boff = (uint32_t)((wn + nj * 16 + b_row) * 80) + kso + b_kb;
                uint32_t th[4];
                ldmatrix_x4(th, sB + boff);
                bH[nj * 2][0] = th[0]; bH[nj * 2][1] = th[1];
                bH[nj * 2 + 1][0] = th[2]; bH[nj * 2 + 1][1] = th[3];
            }

#pragma unroll
            for (int ni = 0; ni < 8; ni++)
#pragma unroll
                for (int mi = 0; mi < 2; mi++)
                    mma16816h(acc[mi][ni], aH[mi], bH[ni][0], bH[ni][1]);
        }
        __syncthreads();
    }

    // ---- epilogue: bias add + store ----
#pragma unroll
    for (int mi = 0; mi < 2; mi++) {
        int row = m0 + wm + mi * 16 + g;
#pragma unroll
        for (int ni = 0; ni < 8; ni++) {
            int col = n0 + wn + ni * 8 + t4 * 2;
            float2 bv = *(const float2*)&bias[col];
            float2 o0, o1;
            o0.x = acc[mi][ni][0] + bv.x;
            o0.y = acc[mi][ni][1] + bv.y;
            o1.x = acc[mi][ni][2] + bv.x;
            o1.y = acc[mi][ni][3] + bv.y;
            *(float2*)&out[(size_t)row * D_OUT + col]       = o0;
            *(float2*)&out[(size_t)(row + 8) * D_OUT + col] = o1;
        }
    }
}

// ============================================================================
// Kernel 4: delta via fp16 mma.sync (unchanged from R10 win).
// ============================================================================
#define K4_STR     144
#define K4_H_BYTES (64 * K4_STR)
#define K4_B_BYTES (128 * K4_STR)
#define K4_SMEM    (K4_H_BYTES + 2 * K4_B_BYTES + 256)

__global__ __launch_bounds__(256) void k4_delta(
    const __half* __restrict__ Bh, float* __restrict__ out)
{
    extern __shared__ char sm4[];
    const uint32_t sbase = smem_u32(sm4);
    const uint32_t sH = sbase;
    const uint32_t sB = sbase + K4_H_BYTES;
    int* stok = (int*)(sm4 + K4_H_BYTES + 2 * K4_B_BYTES);

    const int e     = blockIdx.x >> 5;
    const int stile = blockIdx.x & 31;
    const int cnt   = g_cnt[e];
    const int tid   = threadIdx.x;
    const int wid   = tid >> 5;
    const int lane  = tid & 31;
    const int g     = lane >> 2;
    const int t4    = lane & 3;
    const int sg    = wid & 3;
    const int dg    = wid >> 2;

    if (stile * 64 >= cnt) return;

    const int a_row = ((lane >> 3) & 1) * 8 + (lane & 7);
    const int a_kb  = (lane >> 4) * 16;
    const int b_row = ((lane >> 4) & 1) * 8 + (lane & 7);
    const int b_kb  = ((lane >> 3) & 1) * 16;

    const __half* Be = Bh + (size_t)e * D_OUT * R_RANK;

    for (int s0 = stile * 64; s0 < cnt; s0 += 32 * 64) {
        {
            int slot = tid >> 2;
            int rq   = (tid & 3) * 16;
            int s    = s0 + slot;
            float w = 0.f; int t = -1;
            float vv[16];
#pragma unroll
            for (int j = 0; j < 16; j++) vv[j] = 0.f;
            if (s < cnt) {
                t = g_tok[e * T_TOK + s];
                w = g_wt [e * T_TOK + s];
                const float4* hp = (const float4*)&g_S[(size_t)t * N_COLS + rq];
#pragma unroll
                for (int j = 0; j < 4; j++) *(float4*)&vv[j * 4] = hp[j];
            }
            __half hh[16];
#pragma unroll
            for (int j = 0; j < 16; j++) hh[j] = __float2half_rn(vv[j] * w);
            char* hp = sm4 + slot * K4_STR + rq * 2;
            *(uint4*)hp        = *(uint4*)&hh[0];
            *(uint4*)(hp + 16) = *(uint4*)&hh[8];
            if (rq == 0) stok[slot] = t;
        }

        auto loadB = [&](int i) {
            uint32_t dst = sB + (i & 1) * K4_B_BYTES;
            int d0 = i * 128;
#pragma unroll
            for (int it = 0; it < 4; it++) {
                int q   = tid + it * 256;
                int row = q >> 3;
                int cb  = (q & 7) * 16;
                cp16(dst + row * K4_STR + cb,
                     (const char*)&Be[(size_t)(d0 + row) * R_RANK] + cb);
            }
            CP_COMMIT();
        };

        loadB(0);
        __syncthreads();

        for (int i = 0; i < 16; i++) {
            if (i + 1 < 16) { loadB(i + 1); CP_WAIT(1); }
            else { CP_WAIT(0); }
            __syncthreads();

            const uint32_t stg = sB + (i & 1) * K4_B_BYTES;

            float acc[8][4];
#pragma unroll
            for (int ni = 0; ni < 8; ni++)
#pragma unroll
                for (int r = 0; r < 4; r++) acc[ni][r] = 0.f;

#pragma unroll
            for (int ks = 0; ks < 4; ks++) {
                uint32_t a[4];
                ldmatrix_x4(a, sH + (uint32_t)((sg * 16 + a_row) * K4_STR) + ks * 32 + a_kb);
#pragma unroll
                for (int nj = 0; nj < 4; nj++) {
                    uint32_t bf[4];
                    ldmatrix_x4(bf, stg + (uint32_t)((dg * 64 + nj * 16 + b_row) * K4_STR)
                                     + ks * 32 + b_kb);
                    mma16816h(acc[nj * 2],     a, bf[0], bf[1]);
                    mma16816h(acc[nj * 2 + 1], a, bf[2], bf[3]);
                }
            }

            int t0 = stok[sg * 16 + g];
            int t1 = stok[sg * 16 + g + 8];
            int d0 = i * 128;
#pragma unroll
            for (int ni = 0; ni < 8; ni++) {
                int col = d0 + dg * 64 + ni * 8 + t4 * 2;
                if (t0 >= 0) red_v2(&out[(size_t)t0 * D_OUT + col], acc[ni][0], acc[ni][1]);
                if (t1 >= 0) red_v2(&out[(size_t)t1 * D_OUT + col], acc[ni][2], acc[ni][3]);
            }
            __syncthreads();
        }
    }
}

// ============================================================================
// launch — fork {k1,k2,B-convert} onto side stream, overlapped with {k0,k3};
// join before k4.
// ============================================================================
extern "C" void kernel_launch(void* const* d_in, const int* in_sizes, int n_in,
                              void* d_out, int out_size)
{
    const float* x   = (const float*)d_in[0];
    const float* Wb  = (const float*)d_in[1];
    const float* bb  = (const float*)d_in[2];
    const float* A   = (const float*)d_in[3];
    const float* Bm  = (const float*)d_in[4];
    const float* Wr  = (const float*)d_in[5];
    const int* topk  = (n_in > 6) ? (const int*)d_in[6] : nullptr;
    float* out       = (float*)d_out;

    (void)in_sizes; (void)out_size;

    __half *p_xh, *p_wh, *p_bh;
    cudaGetSymbolAddress((void**)&p_xh, g_xh);
    cudaGetSymbolAddress((void**)&p_wh, g_wh);
    cudaGetSymbolAddress((void**)&p_bh, g_bh);

    static cudaStream_t s1 = nullptr;
    static cudaEvent_t  ev_fork = nullptr, ev_join = nullptr;
    static bool inited = false;
    if (!inited) {
        cudaStreamCreateWithFlags(&s1, cudaStreamNonBlocking);
        cudaEventCreateWithFlags(&ev_fork, cudaEventDisableTiming);
        cudaEventCreateWithFlags(&ev_join, cudaEventDisableTiming);
        cudaFuncSetAttribute(k3_mma_gemm, cudaFuncAttributeMaxDynamicSharedMemorySize, SMEM_K3);
        cudaFuncSetAttribute(k4_delta,    cudaFuncAttributeMaxDynamicSharedMemorySize, K4_SMEM);
        inited = true;
    }

    int n4x = T_TOK * D_IN / 4, n4w = D_OUT * D_IN / 4;
    int n4b = N_EXP * D_OUT * R_RANK / 4;

    // fork side chain: k1 -> k2 -> B convert on s1
    cudaEventRecord(ev_fork, 0);
    cudaStreamWaitEvent(s1, ev_fork, 0);
    k1_small_gemm<<<dim3(2, T_TOK / 128), 256, 0, s1>>>(x, A, Wr);
    k2_router   <<<T_TOK / 128, 128, 0, s1>>>(topk);
    k0_cvt      <<<(n4b + 255) / 256, 256, 0, s1>>>(Bm, p_bh, n4b);
    cudaEventRecord(ev_join, s1);

    // main chain: fused convert + big GEMM
    k0_cvt2<<<592, 256>>>(x, p_xh, n4x, Wb, p_wh, n4w);
    k3_mma_gemm<<<dim3(D_OUT / 128, T_TOK / 64), 128, SMEM_K3>>>(bb, out);

    // join and run delta
    cudaStreamWaitEvent(0, ev_join, 0);
    k4_delta<<<N_EXP * 32, 256, K4_SMEM>>>(p_bh, out);
}

// round 12
// speedup vs baseline: 1.6352x; 1.6352x over previous
#include <cuda_runtime.h>
#include <cuda_fp16.h>
#include <cstdint>

// Problem constants (fixed by setup_inputs)
#define T_TOK   8192      // B*S = 4*2048
#define D_IN    2048
#define D_OUT   2048
#define R_RANK  64
#define N_EXP   16
#define N_COLS  80        // R + E combined small-GEMM width

// ---------------- device scratch (no allocations allowed) ----------------
__device__ float g_S[T_TOK * N_COLS];        // [token][0..63]=res_hidden, [64..79]=router logits
__device__ int   g_cnt[N_EXP];
__device__ int   g_tok[N_EXP * T_TOK];
__device__ float g_wt [N_EXP * T_TOK];
// fp16 copies for the tensor-core GEMMs
__device__ __half g_xh[T_TOK * D_IN];
__device__ __half g_wh[D_OUT * D_IN];
__device__ __half g_bh[N_EXP * D_OUT * R_RANK];

// ---------------- helpers ----------------
__device__ __forceinline__ uint32_t smem_u32(const void* p) {
    uint32_t a;
    asm("{ .reg .u64 t; cvta.to.shared.u64 t, %1; cvt.u32.u64 %0, t; }" : "=r"(a) : "l"(p));
    return a;
}
__device__ __forceinline__ void cp16(uint32_t s, const void* g) {
    asm volatile("cp.async.cg.shared.global [%0], [%1], 16;" :: "r"(s), "l"(g) : "memory");
}
__device__ __forceinline__ void ldmatrix_x4(uint32_t* r, uint32_t addr) {
    asm volatile("ldmatrix.sync.aligned.m8n8.x4.shared.b16 {%0,%1,%2,%3}, [%4];"
                 : "=r"(r[0]), "=r"(r[1]), "=r"(r[2]), "=r"(r[3]) : "r"(addr));
}
__device__ __forceinline__ void mma16816h(float* c, const uint32_t* a, uint32_t b0, uint32_t b1) {
    asm volatile(
        "mma.sync.aligned.m16n8k16.row.col.f32.f16.f16.f32 "
        "{%0,%1,%2,%3}, {%4,%5,%6,%7}, {%8,%9}, {%0,%1,%2,%3};"
        : "+f"(c[0]), "+f"(c[1]), "+f"(c[2]), "+f"(c[3])
        : "r"(a[0]), "r"(a[1]), "r"(a[2]), "r"(a[3]), "r"(b0), "r"(b1));
}
__device__ __forceinline__ void red_v2(float* p, float x, float y) {
    asm volatile("red.global.add.v2.f32 [%0], {%1,%2};"
                 :: "l"(p), "f"(x), "f"(y) : "memory");
}
#define CP_COMMIT() asm volatile("cp.async.commit_group;" ::: "memory")
#define CP_WAIT(n)  asm volatile("cp.async.wait_group %0;" :: "n"(n) : "memory")

// ============================================================================
// Kernel 0: fp32 -> fp16
// ============================================================================
__global__ __launch_bounds__(256) void k0_cvt(
    const float* __restrict__ src, __half* __restrict__ dst, int n4)
{
    int i = blockIdx.x * blockDim.x + threadIdx.x;
    if (i >= n4) return;
    float4 v = *(const float4*)&src[(size_t)i * 4];
    __half h[4];
    h[0] = __float2half_rn(v.x); h[1] = __float2half_rn(v.y);
    h[2] = __float2half_rn(v.z); h[3] = __float2half_rn(v.w);
    *(uint2*)&dst[(size_t)i * 4] = *(uint2*)h;
}

// ============================================================================
// Kernel 1: S = x @ [A^T | W_router^T]  (fp32 SIMT)
// ============================================================================
__global__ __launch_bounds__(256) void k1_small_gemm(
    const float* __restrict__ x,
    const float* __restrict__ A,
    const float* __restrict__ Wr)
{
    __shared__ float xs[128][68];
    __shared__ float ws[40][68];

    const int tid = threadIdx.x;
    if (blockIdx.x == 0 && blockIdx.y == 0 && tid < N_EXP) g_cnt[tid] = 0;

    const int m0 = blockIdx.y * 128;
    const int c0 = blockIdx.x * 40;
    const int tg = tid >> 3;
    const int cg = tid & 7;

    float acc[4][5];
#pragma unroll
    for (int i = 0; i < 4; i++)
#pragma unroll
        for (int j = 0; j < 5; j++) acc[i][j] = 0.f;

    for (int k0 = 0; k0 < D_IN; k0 += 64) {
#pragma unroll
        for (int it = 0; it < 8; it++) {
            int q = tid + it * 256;
            int row = q >> 4;
            int kc = (q & 15) << 2;
            float4 v = *(const float4*)&x[(size_t)(m0 + row) * D_IN + k0 + kc];
            *(float4*)&xs[row][kc] = v;
        }
        for (int q = tid; q < 40 * 16; q += 256) {
            int col = q >> 4;
            int kc = (q & 15) << 2;
            int gc = c0 + col;
            const float* src = (gc < R_RANK) ? (A + (size_t)gc * D_IN)
                                             : (Wr + (size_t)(gc - R_RANK) * D_IN);
            float4 v = *(const float4*)&src[k0 + kc];
            *(float4*)&ws[col][kc] = v;
        }
        __syncthreads();

#pragma unroll 16
        for (int kk = 0; kk < 64; kk++) {
            float av[4], bv[5];
#pragma unroll
            for (int i = 0; i < 4; i++) av[i] = xs[tg * 4 + i][kk];
#pragma unroll
            for (int j = 0; j < 5; j++) bv[j] = ws[cg * 5 + j][kk];
#pragma unroll
            for (int i = 0; i < 4; i++)
#pragma unroll
                for (int j = 0; j < 5; j++) acc[i][j] += av[i] * bv[j];
        }
        __syncthreads();
    }

#pragma unroll
    for (int i = 0; i < 4; i++) {
        size_t base = (size_t)(m0 + tg * 4 + i) * N_COLS + c0 + cg * 5;
#pragma unroll
        for (int j = 0; j < 5; j++) g_S[base + j] = acc[i][j];
    }
}

// ============================================================================
// Kernel 2: softmax + top-k + scatter
// ============================================================================
__global__ __launch_bounds__(128) void k2_router(const int* __restrict__ topk_ptr)
{
    int t = blockIdx.x * blockDim.x + threadIdx.x;
    if (t >= T_TOK) return;

    float p[N_EXP];
    float mx = -1e30f;
#pragma unroll
    for (int e = 0; e < N_EXP; e++) {
        p[e] = g_S[(size_t)t * N_COLS + R_RANK + e];
        mx = fmaxf(mx, p[e]);
    }
    float sum = 0.f;
#pragma unroll
    for (int e = 0; e < N_EXP; e++) { p[e] = __expf(p[e] - mx); sum += p[e]; }
    float inv = 1.f / sum;
#pragma unroll
    for (int e = 0; e < N_EXP; e++) p[e] *= inv;

    int k = topk_ptr ? *topk_ptr : 2;

    if (k > 0 && k < N_EXP) {
        unsigned sel = 0;
        float ssum = 0.f;
        for (int it = 0; it < k; it++) {
            int best = -1; float bv = -1.f;
#pragma unroll
            for (int e = 0; e < N_EXP; e++)
                if (!((sel >> e) & 1u) && p[e] > bv) { bv = p[e]; best = e; }
            sel |= 1u << best;
            ssum += bv;
        }
        float denom = 1.f / (ssum + 1e-6f);
#pragma unroll
        for (int e = 0; e < N_EXP; e++) {
            if ((sel >> e) & 1u) {
                float w = p[e] * denom;
                int slot = atomicAdd(&g_cnt[e], 1);
                g_tok[e * T_TOK + slot] = t;
                g_wt [e * T_TOK + slot] = w;
            }
        }
    } else {
#pragma unroll
        for (int e = 0; e < N_EXP; e++) {
            int slot = atomicAdd(&g_cnt[e], 1);
            g_tok[e * T_TOK + slot] = t;
            g_wt [e * T_TOK + slot] = p[e];
        }
    }
}

// ============================================================================
// Kernel 3: base GEMM via mma.sync fp16: out = xh @ wh^T + b
// CTA tile 128x128, BK=32, 8 warps (2x4), warp tile 64x32, 3-stage cp.async.
// L2 swizzle: 8 consecutive bids share one n-tile (B hot in L2).
// ============================================================================
#define BK       32
#define NCHUNK   (D_IN / BK)                 // 64
#define MAT_BYTES (128 * 80)                 // 10240
#define STAGE_BYTES (2 * MAT_BYTES)          // 20480 (Ah | Bh)
#define SMEM_DYN (3 * STAGE_BYTES)           // 61440

__global__ __launch_bounds__(256, 2) void k3_mma_gemm(
    const float* __restrict__ bias, float* __restrict__ out)
{
    extern __shared__ char sm[];
    const int tid  = threadIdx.x;
    const int wid  = tid >> 5;
    const int lane = tid & 31;
    const int g    = lane >> 2;      // group id 0..7
    const int t4   = lane & 3;       // thread-in-group 0..3

    // L2 swizzle: bid -> (mtile, ntile); 8 consecutive bids share ntile.
    const int bid   = blockIdx.x;
    const int group = bid >> 9;          // 64 bids per n-column... see below
    // layout: 16 n-tiles x 64 m-tiles = 1024 CTAs.
    // chunk of 8 m-tiles x 16 n-tiles = 128 bids per super-row.
    const int srow  = bid >> 7;          // 0..7 (8 super-rows of 8 m-tiles)
    const int inner = bid & 127;
    const int ntile = inner >> 3;        // 0..15
    const int mtile = srow * 8 + (inner & 7);
    (void)group;

    const int m0 = mtile * 128;
    const int n0 = ntile * 128;
    const int wm = (wid >> 2) * 64;  // warp M offset within CTA
    const int wn = (wid & 3) * 32;   // warp N offset within CTA

    const uint32_t sbase = smem_u32(sm);

    const int a_row = ((lane >> 3) & 1) * 8 + (lane & 7);
    const int a_kb  = (lane >> 4) * 16;
    const int b_row = ((lane >> 4) & 1) * 8 + (lane & 7);
    const int b_kb  = ((lane >> 3) & 1) * 16;

    float acc[4][4][4];
#pragma unroll
    for (int mi = 0; mi < 4; mi++)
#pragma unroll
        for (int ni = 0; ni < 4; ni++)
#pragma unroll
            for (int r = 0; r < 4; r++) acc[mi][ni][r] = 0.f;

    auto load_chunk = [&](int c) {
        const int p  = c % 3;
        const int k0 = c * BK;
#pragma unroll
        for (int it = 0; it < 4; it++) {
            int q    = tid + it * 256;          // 0..1023
            int mat  = q >> 9;                  // 0: Ah, 1: Bh
            int row  = (q >> 2) & 127;
            int quad = q & 3;
            const __half* src = mat ? g_wh : g_xh;
            int grow = (mat ? n0 : m0) + row;
            uint32_t saddr = sbase + p * STAGE_BYTES + mat * MAT_BYTES
                           + row * 80 + quad * 16;
            cp16(saddr, &src[(size_t)grow * D_IN + k0 + quad * 8]);
        }
        CP_COMMIT();
    };

    load_chunk(0);
    load_chunk(1);

    for (int c = 0; c < NCHUNK; c++) {
        if (c + 2 < NCHUNK) { load_chunk(c + 2); CP_WAIT(2); }
        else if (c + 1 < NCHUNK) { CP_WAIT(1); }
        else { CP_WAIT(0); }
        __syncthreads();

        const uint32_t stg = sbase + (c % 3) * STAGE_BYTES;
        const uint32_t sAh = stg;
        const uint32_t sBh = stg + MAT_BYTES;

#pragma unroll
        for (int ks = 0; ks < 2; ks++) {
            const uint32_t kso = ks * 32;

            uint32_t aH[4][4];
#pragma unroll
            for (int mi = 0; mi < 4; mi++) {
                uint32_t aoff = (uint32_t)((wm + mi * 16 + a_row) * 80) + kso + a_kb;
                ldmatrix_x4(aH[mi], sAh + aoff);
            }
            uint32_t bH[4][2];
#pragma unroll
            for (int nj = 0; nj < 2; nj++) {
                uint32_t boff = (uint32_t)((wn + nj * 16 + b_row) * 80) + kso + b_kb;
                uint32_t th[4];
                ldmatrix_x4(th, sBh + boff);
                bH[nj * 2][0] = th[0]; bH[nj * 2][1] = th[1];
                bH[nj * 2 + 1][0] = th[2]; bH[nj * 2 + 1][1] = th[3];
            }

#pragma unroll
            for (int ni = 0; ni < 4; ni++)
#pragma unroll
                for (int mi = 0; mi < 4; mi++)
                    mma16816h(acc[mi][ni], aH[mi], bH[ni][0], bH[ni][1]);
        }
        __syncthreads();
    }

#pragma unroll
    for (int mi = 0; mi < 4; mi++) {
        int row = m0 + wm + mi * 16 + g;
#pragma unroll
        for (int ni = 0; ni < 4; ni++) {
            int col = n0 + wn + ni * 8 + t4 * 2;
            float2 bv = *(const float2*)&bias[col];
            float2 o0, o1;
            o0.x = acc[mi][ni][0] + bv.x;
            o0.y = acc[mi][ni][1] + bv.y;
            o1.x = acc[mi][ni][2] + bv.x;
            o1.y = acc[mi][ni][3] + bv.y;
            *(float2*)&out[(size_t)row * D_OUT + col]       = o0;
            *(float2*)&out[(size_t)(row + 8) * D_OUT + col] = o1;
        }
    }
}

// ============================================================================
// Kernel 4: delta via fp16 mma.sync (R10 version, unchanged).
// ============================================================================
#define K4_STR     144
#define K4_H_BYTES (64 * K4_STR)
#define K4_B_BYTES (128 * K4_STR)
#define K4_SMEM    (K4_H_BYTES + 2 * K4_B_BYTES + 256)

__global__ __launch_bounds__(256) void k4_delta(
    const __half* __restrict__ Bh, float* __restrict__ out)
{
    extern __shared__ char sm4[];
    const uint32_t sbase = smem_u32(sm4);
    const uint32_t sH = sbase;
    const uint32_t sB = sbase + K4_H_BYTES;
    int* stok = (int*)(sm4 + K4_H_BYTES + 2 * K4_B_BYTES);

    const int e     = blockIdx.x >> 5;
    const int stile = blockIdx.x & 31;
    const int cnt   = g_cnt[e];
    const int tid   = threadIdx.x;
    const int wid   = tid >> 5;
    const int lane  = tid & 31;
    const int g     = lane >> 2;
    const int t4    = lane & 3;
    const int sg    = wid & 3;
    const int dg    = wid >> 2;

    if (stile * 64 >= cnt) return;

    const int a_row = ((lane >> 3) & 1) * 8 + (lane & 7);
    const int a_kb  = (lane >> 4) * 16;
    const int b_row = ((lane >> 4) & 1) * 8 + (lane & 7);
    const int b_kb  = ((lane >> 3) & 1) * 16;

    const __half* Be = Bh + (size_t)e * D_OUT * R_RANK;

    for (int s0 = stile * 64; s0 < cnt; s0 += 32 * 64) {
        {
            int slot = tid >> 2;
            int rq   = (tid & 3) * 16;
            int s    = s0 + slot;
            float w = 0.f; int t = -1;
            float vv[16];
#pragma unroll
            for (int j = 0; j < 16; j++) vv[j] = 0.f;
            if (s < cnt) {
                t = g_tok[e * T_TOK + s];
                w = g_wt [e * T_TOK + s];
                const float4* hp = (const float4*)&g_S[(size_t)t * N_COLS + rq];
#pragma unroll
                for (int j = 0; j < 4; j++) *(float4*)&vv[j * 4] = hp[j];
            }
            __half hh[16];
#pragma unroll
            for (int j = 0; j < 16; j++) hh[j] = __float2half_rn(vv[j] * w);
            char* hp = sm4 + slot * K4_STR + rq * 2;
            *(uint4*)hp        = *(uint4*)&hh[0];
            *(uint4*)(hp + 16) = *(uint4*)&hh[8];
            if (rq == 0) stok[slot] = t;
        }

        auto loadB = [&](int i) {
            uint32_t dst = sB + (i & 1) * K4_B_BYTES;
            int d0 = i * 128;
#pragma unroll
            for (int it = 0; it < 4; it++) {
                int q   = tid + it * 256;
                int row = q >> 3;
                int cb  = (q & 7) * 16;
                cp16(dst + row * K4_STR + cb,
                     (const char*)&Be[(size_t)(d0 + row) * R_RANK] + cb);
            }
            CP_COMMIT();
        };

        loadB(0);
        __syncthreads();

        for (int i = 0; i < 16; i++) {
            if (i + 1 < 16) { loadB(i + 1); CP_WAIT(1); }
            else { CP_WAIT(0); }
            __syncthreads();

            const uint32_t stg = sB + (i & 1) * K4_B_BYTES;

            float acc[8][4];
#pragma unroll
            for (int ni = 0; ni < 8; ni++)
#pragma unroll
                for (int r = 0; r < 4; r++) acc[ni][r] = 0.f;

#pragma unroll
            for (int ks = 0; ks < 4; ks++) {
                uint32_t a[4];
                ldmatrix_x4(a, sH + (uint32_t)((sg * 16 + a_row) * K4_STR) + ks * 32 + a_kb);
#pragma unroll
                for (int nj = 0; nj < 4; nj++) {
                    uint32_t bf[4];
                    ldmatrix_x4(bf, stg + (uint32_t)((dg * 64 + nj * 16 + b_row) * K4_STR)
                                     + ks * 32 + b_kb);
                    mma16816h(acc[nj * 2],     a, bf[0], bf[1]);
                    mma16816h(acc[nj * 2 + 1], a, bf[2], bf[3]);
                }
            }

            int t0 = stok[sg * 16 + g];
            int t1 = stok[sg * 16 + g + 8];
            int d0 = i * 128;
#pragma unroll
            for (int ni = 0; ni < 8; ni++) {
                int col = d0 + dg * 64 + ni * 8 + t4 * 2;
                if (t0 >= 0) red_v2(&out[(size_t)t0 * D_OUT + col], acc[ni][0], acc[ni][1]);
                if (t1 >= 0) red_v2(&out[(size_t)t1 * D_OUT + col], acc[ni][2], acc[ni][3]);
            }
            __syncthreads();
        }
    }
}

// ============================================================================
// launch — fork {k1,k2,B-convert} onto side stream, overlapped with {k0,k3};
// join before k4.
// ============================================================================
extern "C" void kernel_launch(void* const* d_in, const int* in_sizes, int n_in,
                              void* d_out, int out_size)
{
    const float* x   = (const float*)d_in[0];
    const float* Wb  = (const float*)d_in[1];
    const float* bb  = (const float*)d_in[2];
    const float* A   = (const float*)d_in[3];
    const float* Bm  = (const float*)d_in[4];
    const float* Wr  = (const float*)d_in[5];
    const int* topk  = (n_in > 6) ? (const int*)d_in[6] : nullptr;
    float* out       = (float*)d_out;

    (void)in_sizes; (void)out_size;

    __half *p_xh, *p_wh, *p_bh;
    cudaGetSymbolAddress((void**)&p_xh, g_xh);
    cudaGetSymbolAddress((void**)&p_wh, g_wh);
    cudaGetSymbolAddress((void**)&p_bh, g_bh);

    static cudaStream_t s1 = nullptr;
    static cudaEvent_t  ev_fork = nullptr, ev_join = nullptr;
    static bool inited = false;
    if (!inited) {
        cudaStreamCreateWithFlags(&s1, cudaStreamNonBlocking);
        cudaEventCreateWithFlags(&ev_fork, cudaEventDisableTiming);
        cudaEventCreateWithFlags(&ev_join, cudaEventDisableTiming);
        cudaFuncSetAttribute(k3_mma_gemm, cudaFuncAttributeMaxDynamicSharedMemorySize, SMEM_DYN);
        cudaFuncSetAttribute(k4_delta,    cudaFuncAttributeMaxDynamicSharedMemorySize, K4_SMEM);
        inited = true;
    }

    int n4x = T_TOK * D_IN / 4, n4w = D_OUT * D_IN / 4;
    int n4b = N_EXP * D_OUT * R_RANK / 4;

    // fork side chain: k1 -> k2 -> B convert on s1
    cudaEventRecord(ev_fork, 0);
    cudaStreamWaitEvent(s1, ev_fork, 0);
    k1_small_gemm<<<dim3(2, T_TOK / 128), 256, 0, s1>>>(x, A, Wr);
    k2_router   <<<T_TOK / 128, 128, 0, s1>>>(topk);
    k0_cvt      <<<(n4b + 255) / 256, 256, 0, s1>>>(Bm, p_bh, n4b);
    cudaEventRecord(ev_join, s1);

    // main chain: converts + big GEMM
    k0_cvt<<<(n4x + 255) / 256, 256>>>(x,  p_xh, n4x);
    k0_cvt<<<(n4w + 255) / 256, 256>>>(Wb, p_wh, n4w);
    k3_mma_gemm<<<1024, 256, SMEM_DYN>>>(bb, out);

    // join and run delta
    cudaStreamWaitEvent(0, ev_join, 0);
    k4_delta<<<N_EXP * 32, 256, K4_SMEM>>>(p_bh, out);
}